// round 11
// baseline (speedup 1.0000x reference)
#include <cuda_runtime.h>
#include <cuda_fp16.h>

// ---------------- problem-size constants (fixed by the dataset) -------------
#define N_MAX   100032      // >= 100000 nodes
#define E_MAX   1600000
#define E_PAD   2001600     // E + 4*N padding headroom
#define D       50          // attrs
#define STRH    64          // padded row stride of fp16 buffers (64 halves = 128B)
#define NITER   30
#define SCAN_B  256
#define PBLK    888         // persistent grid: <=148 SMs x 6 blocks (residency-safe)

// ---------------- static device scratch (no allocations allowed) ------------
// Invariants at call entry (static zero on load; restored by each call):
//   g_deg == 0 (zeroed in k_persist), g_meansum == 0, g_ctr == 0, g_bctr == 0.
//   g_bgen is monotonic across launches (never reset; only relative use).
__device__ int    g_deg[N_MAX];
__device__ int2   g_span[N_MAX];         // {start, end} per node (one 8B load)
__device__ int    g_rank[E_MAX];         // per-edge rank within its row
__device__ int    g_partial[512];
__device__ int    g_ctr;                 // scan grid-barrier arrival counter
__device__ int    g_bctr;                // persistent barrier counter (self-resets)
__device__ volatile int g_bgen;          // persistent barrier generation (monotonic)
__device__ int    g_csr[E_PAD];          // col*STRH (half offset); dummies -> row n
__device__ float  g_dinv[N_MAX];
__device__ unsigned char g_isknown[N_MAX];   // idempotent sets; never cleared
__device__ float  g_meansum[64];
__device__ float  g_mean[64];            // pads [50,64) stay 0 forever
__device__ float  g_alpha[64];
__device__ float  g_oma[64];
__device__ float  g_beta[64];
__device__ float  g_omb[64];
__device__ float  g_colsum[(NITER + 1) * 64];
__device__ int    g_need_colmean;        // set iff any alpha != 1
__device__ int    g_need_beta;
// zero-initialized; rows >= n are NEVER written, so dummy gathers read 0.
__device__ __half g_bufA[(size_t)N_MAX * STRH];
__device__ __half g_bufB[(size_t)N_MAX * STRH];

// L1-bypassing gather (required: persistent kernel has no per-launch L1 flush,
// so cross-SM ping-pong writes would be stale in L1). Returns converted fp32.
__device__ __forceinline__ float2 ld_cg_h2f(const __half* p) {
    unsigned int u;
    asm volatile("ld.global.cg.b32 %0, [%1];" : "=r"(u) : "l"(p));
    __half2 h = *reinterpret_cast<__half2*>(&u);
    return __half22float2(h);
}

// ---------------- kernel 1: degrees(+rank) + isknown + mean partials --------
__global__ void k_deg_known_mean(const int* __restrict__ row,
                                 const int* __restrict__ km,
                                 const float* __restrict__ x, int E, int K) {
    int i = blockIdx.x * blockDim.x + threadIdx.x;
    if (i < E) g_rank[i] = atomicAdd(&g_deg[row[i]], 1);
    if (i < K) g_isknown[km[i]] = 1;
    if (blockIdx.x < 100) {
        __shared__ float sm[64];
        if (threadIdx.x < 64) sm[threadIdx.x] = 0.f;
        __syncthreads();
        int lane = threadIdx.x & 31;
        int w  = (blockIdx.x * blockDim.x + threadIdx.x) >> 5;
        int nw = (100 * blockDim.x) >> 5;
        float2 acc = make_float2(0.f, 0.f);
        for (int k = w; k < K; k += nw) {
            int idx = km[k];
            if (lane < 25) {
                float2 vv = *(const float2*)(x + (size_t)idx * D + 2 * lane);
                acc.x += vv.x; acc.y += vv.y;
            }
        }
        if (lane < 25) {
            atomicAdd(&sm[2 * lane],     acc.x);
            atomicAdd(&sm[2 * lane + 1], acc.y);
        }
        __syncthreads();
        if (threadIdx.x < D) atomicAdd(&g_meansum[threadIdx.x], sm[threadIdx.x]);
    }
}

// ---------------- kernel 2: fused scan + spans + params (grid barrier) ------
__global__ void k_scan_params(int n, const float* __restrict__ eta,
                              const float* __restrict__ theta, int K) {
    __shared__ int s[SCAN_B];
    __shared__ int red[SCAN_B];
    __shared__ int fc, fb;
    int b = blockIdx.x, t = threadIdx.x;
    int i = b * SCAN_B + t;
    int nb = gridDim.x;

    if (i < (NITER + 1) * 64) g_colsum[i] = 0.f;

    int dg = (i < n) ? g_deg[i] : 0;
    if (i < n) g_dinv[i] = (dg > 0) ? rsqrtf((float)dg) : 0.f;
    int v = (dg + 3) & ~3;                      // padded length
    s[t] = v;
    __syncthreads();
    for (int d = 1; d < SCAN_B; d <<= 1) {
        int tmp = (t >= d) ? s[t - d] : 0;
        __syncthreads();
        s[t] += tmp;
        __syncthreads();
    }
    int excl = s[t] - v;
    if (t == SCAN_B - 1) {
        g_partial[b] = s[SCAN_B - 1];
        __threadfence();
    }
    __syncthreads();

    if (b == 0) {
        if (t == 0) { fc = 0; fb = 0; }
        __syncthreads();
        if (t < D) {
            g_mean[t] = g_meansum[t] / (float)K;
            float nf = (float)n;
            float a  = (nf - 1.f) / (theta[t] * nf + (nf - 1.f));
            float ia = 1.f / a;
            float bb = ia / (ia + eta[t]);
            g_alpha[t] = a;  g_oma[t] = 1.f - a;
            g_beta[t]  = bb; g_omb[t] = 1.f - bb;
            if (a  != 1.f) atomicExch(&fc, 1);
            if (bb != 1.f) atomicExch(&fb, 1);
        }
        __syncthreads();
        if (t == 0) { g_need_colmean = fc; g_need_beta = fb; }
    }

    if (t == 0) {
        atomicAdd(&g_ctr, 1);
        while (*(volatile int*)&g_ctr < nb) { }
    }
    __syncthreads();
    __threadfence();

    int local = 0;
    for (int j = t; j < b; j += SCAN_B) local += g_partial[j];
    red[t] = local;
    __syncthreads();
    for (int off = SCAN_B / 2; off > 0; off >>= 1) {
        if (t < off) red[t] += red[t + off];
        __syncthreads();
    }
    int base = red[0];

    if (i < n) {
        int s0 = base + excl;
        g_span[i] = make_int2(s0, s0 + v);
    }
}

// ---------------- kernel 3: fused scatter + pad-fill + y0 init --------------
__global__ void k_build_init(const int* __restrict__ row, const int* __restrict__ col,
                             const float* __restrict__ x, int n, int E) {
    int tidg = blockIdx.x * blockDim.x + threadIdx.x;

    if (tidg < E) {
        int r = row[tidg];
        g_csr[g_span[r].x + g_rank[tidg]] = col[tidg] * STRH;
    }

    if (tidg < n) {
        int2 sp = g_span[tidg];
        int dummy = n * STRH;
        for (int j = sp.x + g_deg[tidg]; j < sp.y; ++j) g_csr[j] = dummy;
    }

    int gw   = tidg >> 5;
    int lane = threadIdx.x & 31;
    __shared__ float cs[64];
    int needc = g_need_colmean;
    if (needc) { if (threadIdx.x < 64) cs[threadIdx.x] = 0.f; __syncthreads(); }
    float2 v = make_float2(0.f, 0.f);
    if (gw < n) {
        if (lane < 25 && g_isknown[gw])
            v = *(const float2*)(x + (size_t)gw * D + 2 * lane);
        float2 m = ((const float2*)g_mean)[lane];
        v.x -= m.x; v.y -= m.y;
        float di = g_dinv[gw];
        if (lane < 25)
            *(__half2*)(g_bufA + (size_t)gw * STRH + 2 * lane) =
                __floats2half2_rn(di * v.x, di * v.y);
    }
    if (needc) {
        if (gw < n && lane < 25) {
            atomicAdd(&cs[2 * lane],     v.x);
            atomicAdd(&cs[2 * lane + 1], v.y);
        }
        __syncthreads();
        if (threadIdx.x < D) atomicAdd(&g_colsum[threadIdx.x], cs[threadIdx.x]);
    }
}

// ---------------- persistent kernel: ALL 30 iterations, grid-sync between ---
__global__ __launch_bounds__(256, 6) void k_persist(const float* __restrict__ x,
                                                    float* __restrict__ fout,
                                                    int n, float invn) {
    const int tid   = threadIdx.x;
    const int lane  = tid & 31;
    const int tidg0 = blockIdx.x * blockDim.x + tid;
    const int nthr  = gridDim.x * blockDim.x;
    const int wid0  = tidg0 >> 5;
    const int W     = nthr >> 5;
    const int nb    = gridDim.x;
    const int needc = g_need_colmean;
    const int needb = g_need_beta;
    __shared__ float cs[64];

    // restore invariant for the NEXT call (g_deg readers are all in the past)
    for (int i = tidg0; i < n; i += nthr) g_deg[i] = 0;

    #pragma unroll 1
    for (int t = 0; t < NITER; ++t) {
        const int last = (t == NITER - 1);
        const __half* in  = (t & 1) ? g_bufB : g_bufA;
        __half*       out = (t & 1) ? g_bufA : g_bufB;
        const float* cs_in  = g_colsum + t * 64;
        float*       cs_out = g_colsum + (t + 1) * 64;

        if (needc) {
            if (tid < 64) cs[tid] = 0.f;
            __syncthreads();
        }

        #pragma unroll 1
        for (int gw = wid0; gw < n; gw += W) {
            int2 sp = g_span[gw];                 // read-only: .ca safe
            int s = sp.x, e = sp.y;               // 16B aligned, mult of 4
            const __half* inp = in + 2 * lane;
            float2 acc = make_float2(0.f, 0.f);
            int i = s;
            for (; i + 8 <= e; i += 8) {
                int4 c0 = *(const int4*)(g_csr + i);
                int4 c1 = *(const int4*)(g_csr + i + 4);
                float2 v0 = ld_cg_h2f(inp + c0.x);
                float2 v1 = ld_cg_h2f(inp + c0.y);
                float2 v2 = ld_cg_h2f(inp + c0.z);
                float2 v3 = ld_cg_h2f(inp + c0.w);
                float2 v4 = ld_cg_h2f(inp + c1.x);
                float2 v5 = ld_cg_h2f(inp + c1.y);
                float2 v6 = ld_cg_h2f(inp + c1.z);
                float2 v7 = ld_cg_h2f(inp + c1.w);
                acc.x += v0.x + v1.x + v2.x + v3.x + v4.x + v5.x + v6.x + v7.x;
                acc.y += v0.y + v1.y + v2.y + v3.y + v4.y + v5.y + v6.y + v7.y;
            }
            for (; i < e; i += 4) {
                int4 c0 = *(const int4*)(g_csr + i);
                float2 v0 = ld_cg_h2f(inp + c0.x);
                float2 v1 = ld_cg_h2f(inp + c0.y);
                float2 v2 = ld_cg_h2f(inp + c0.z);
                float2 v3 = ld_cg_h2f(inp + c0.w);
                acc.x += v0.x + v1.x + v2.x + v3.x;
                acc.y += v0.y + v1.y + v2.y + v3.y;
            }
            float di = g_dinv[gw];
            float2 v;
            if (needc) {
                float2 a  = ((const float2*)g_alpha)[lane];
                float2 om = ((const float2*)g_oma)[lane];
                v.x = fmaf(a.x, di * acc.x, om.x * (cs_in[2 * lane]     * invn));
                v.y = fmaf(a.y, di * acc.y, om.y * (cs_in[2 * lane + 1] * invn));
            } else {
                v.x = di * acc.x;                 // alpha == 1 exactly
                v.y = di * acc.y;
            }
            if (needb && g_isknown[gw]) {
                float2 b  = ((const float2*)g_beta)[lane];
                float2 ob = ((const float2*)g_omb)[lane];
                float2 m  = ((const float2*)g_mean)[lane];
                float2 xv = make_float2(0.f, 0.f);
                if (lane < 25) xv = *(const float2*)(x + (size_t)gw * D + 2 * lane);
                v.x = b.x * v.x + ob.x * (xv.x - m.x);
                v.y = b.y * v.y + ob.y * (xv.y - m.y);
            }
            if (last) {
                float2 m = ((const float2*)g_mean)[lane];
                if (lane < 25)
                    *(float2*)(fout + (size_t)gw * D + 2 * lane) =
                        make_float2(v.x + m.x, v.y + m.y);
            } else {
                if (lane < 25)
                    *(__half2*)(out + (size_t)gw * STRH + 2 * lane) =
                        __floats2half2_rn(di * v.x, di * v.y);
            }
            if (needc && lane < 25) {
                atomicAdd(&cs[2 * lane],     v.x);
                atomicAdd(&cs[2 * lane + 1], v.y);
            }
        }

        if (needc && !last) {
            __syncthreads();
            if (tid < D) atomicAdd(&cs_out[tid], cs[tid]);
        }

        if (!last) {
            // grid barrier: generation counter, reset-before-release.
            __syncthreads();
            if (tid == 0) {
                int g = g_bgen;               // read gen BEFORE arriving
                __threadfence();              // order read + publish our writes
                if (atomicAdd(&g_bctr, 1) == nb - 1) {
                    g_bctr = 0;               // reset BEFORE release
                    __threadfence();
                    g_bgen = g + 1;           // release (monotonic, never reset)
                } else {
                    while (g_bgen == g) { }
                }
                __threadfence();
            }
            __syncthreads();
        }
    }

    // restore invariants for the NEXT call
    if (tidg0 < 64) g_meansum[tidg0] = 0.f;
    if (tidg0 == 0) { g_ctr = 0; }            // g_bctr already 0; g_bgen monotonic
}

// ---------------- launcher ---------------------------------------------------
extern "C" void kernel_launch(void* const* d_in, const int* in_sizes, int n_in,
                              void* d_out, int out_size) {
    const float* x     = (const float*)d_in[0];
    const float* eta   = (const float*)d_in[1];
    const float* theta = (const float*)d_in[2];
    const int*   ei    = (const int*)d_in[3];
    const int*   km    = (const int*)d_in[4];

    int dd = in_sizes[1];              // 50
    int n  = in_sizes[0] / dd;         // 100000
    int E  = in_sizes[3] / 2;          // 1600000
    int K  = in_sizes[4];              // 50000
    const int* row = ei;
    const int* col = ei + E;

    const int TB = 256;
    int nbN = (n + TB - 1) / TB;       // 391 — one resident wave (safe to spin)
    int nbE = (E + TB - 1) / TB;
    int nbW = (n * 32 + TB - 1) / TB;  // warp-per-node grid for build_init

    k_deg_known_mean<<<nbE, TB>>>(row, km, x, E, K);
    k_scan_params   <<<nbN, TB>>>(n, eta, theta, K);
    k_build_init    <<<nbW, TB>>>(row, col, x, n, E);

    float invn = 1.f / (float)n;
    k_persist<<<PBLK, TB>>>(x, (float*)d_out, n, invn);
}

// round 13
// speedup vs baseline: 1.1176x; 1.1176x over previous
#include <cuda_runtime.h>
#include <cuda_fp16.h>

// ---------------- problem-size constants (fixed by the dataset) -------------
#define N_MAX   100032      // >= 100000 nodes
#define E_MAX   1600000
#define E_PAD   2001600     // E + 4*N padding headroom
#define D       50          // attrs
#define STRH    64          // padded row stride of fp16 buffers (64 halves = 128B)
#define NITER   30
#define SCAN_B  256
#define PBLK    888         // one-wave grid for k_iter: 148 SMs x 6 blocks

// ---------------- static device scratch (no allocations allowed) ------------
// Invariants at call entry (static zero on load; restored by each call):
//   g_deg == 0 (zeroed in k_iter t==0), g_meansum == 0 and g_ctr == 0
//   (zeroed in k_iter t==NITER-1). g_colsum zeroed inside k_scan_params.
__device__ int    g_deg[N_MAX];
__device__ int2   g_span[N_MAX];         // {start, end} per node (one 8B load)
__device__ int    g_rank[E_MAX];         // per-edge rank within its row
__device__ int    g_partial[512];
__device__ int    g_ctr;                 // scan grid-barrier arrival counter
__device__ int    g_csr[E_PAD];          // col*STRH (half offset); dummies -> row n
__device__ float  g_dinv[N_MAX];
__device__ unsigned char g_isknown[N_MAX];   // idempotent sets; never cleared
__device__ float  g_meansum[64];
__device__ float  g_mean[64];            // pads [50,64) stay 0 forever
__device__ float  g_alpha[64];
__device__ float  g_oma[64];
__device__ float  g_beta[64];
__device__ float  g_omb[64];
__device__ float  g_colsum[(NITER + 1) * 64];
__device__ int    g_need_colmean;        // set iff any alpha != 1
__device__ int    g_need_beta;
// zero-initialized; rows >= n are NEVER written, so dummy gathers read 0.
__device__ __half g_bufA[(size_t)N_MAX * STRH];
__device__ __half g_bufB[(size_t)N_MAX * STRH];

// ---------------- kernel 1: degrees(+rank) + isknown + mean partials --------
__global__ void k_deg_known_mean(const int* __restrict__ row,
                                 const int* __restrict__ km,
                                 const float* __restrict__ x, int E, int K) {
    int i = blockIdx.x * blockDim.x + threadIdx.x;
    if (i < E) g_rank[i] = atomicAdd(&g_deg[row[i]], 1);
    if (i < K) g_isknown[km[i]] = 1;
    if (blockIdx.x < 100) {
        __shared__ float sm[64];
        if (threadIdx.x < 64) sm[threadIdx.x] = 0.f;
        __syncthreads();
        int lane = threadIdx.x & 31;
        int w  = (blockIdx.x * blockDim.x + threadIdx.x) >> 5;
        int nw = (100 * blockDim.x) >> 5;
        float2 acc = make_float2(0.f, 0.f);
        for (int k = w; k < K; k += nw) {
            int idx = km[k];
            if (lane < 25) {
                float2 vv = *(const float2*)(x + (size_t)idx * D + 2 * lane);
                acc.x += vv.x; acc.y += vv.y;
            }
        }
        if (lane < 25) {
            atomicAdd(&sm[2 * lane],     acc.x);
            atomicAdd(&sm[2 * lane + 1], acc.y);
        }
        __syncthreads();
        if (threadIdx.x < D) atomicAdd(&g_meansum[threadIdx.x], sm[threadIdx.x]);
    }
}

// ---------------- kernel 2: fused scan + spans + params (grid barrier) ------
// grid = ceil(n/256) = 391 blocks — fits in one resident wave; spin is safe.
__global__ void k_scan_params(int n, const float* __restrict__ eta,
                              const float* __restrict__ theta, int K) {
    __shared__ int s[SCAN_B];
    __shared__ int red[SCAN_B];
    __shared__ int fc, fb;
    int b = blockIdx.x, t = threadIdx.x;
    int i = b * SCAN_B + t;
    int nb = gridDim.x;

    if (i < (NITER + 1) * 64) g_colsum[i] = 0.f;

    int dg = (i < n) ? g_deg[i] : 0;
    if (i < n) g_dinv[i] = (dg > 0) ? rsqrtf((float)dg) : 0.f;
    int v = (dg + 3) & ~3;                      // padded length
    s[t] = v;
    __syncthreads();
    for (int d = 1; d < SCAN_B; d <<= 1) {
        int tmp = (t >= d) ? s[t - d] : 0;
        __syncthreads();
        s[t] += tmp;
        __syncthreads();
    }
    int excl = s[t] - v;
    if (t == SCAN_B - 1) {
        g_partial[b] = s[SCAN_B - 1];
        __threadfence();
    }
    __syncthreads();

    if (b == 0) {
        if (t == 0) { fc = 0; fb = 0; }
        __syncthreads();
        if (t < D) {
            g_mean[t] = g_meansum[t] / (float)K;
            float nf = (float)n;
            float a  = (nf - 1.f) / (theta[t] * nf + (nf - 1.f));
            float ia = 1.f / a;
            float bb = ia / (ia + eta[t]);
            g_alpha[t] = a;  g_oma[t] = 1.f - a;
            g_beta[t]  = bb; g_omb[t] = 1.f - bb;
            if (a  != 1.f) atomicExch(&fc, 1);
            if (bb != 1.f) atomicExch(&fb, 1);
        }
        __syncthreads();
        if (t == 0) { g_need_colmean = fc; g_need_beta = fb; }
    }

    if (t == 0) {
        atomicAdd(&g_ctr, 1);
        while (*(volatile int*)&g_ctr < nb) { }
    }
    __syncthreads();
    __threadfence();

    int local = 0;
    for (int j = t; j < b; j += SCAN_B) local += g_partial[j];
    red[t] = local;
    __syncthreads();
    for (int off = SCAN_B / 2; off > 0; off >>= 1) {
        if (t < off) red[t] += red[t + off];
        __syncthreads();
    }
    int base = red[0];

    if (i < n) {
        int s0 = base + excl;
        g_span[i] = make_int2(s0, s0 + v);
    }
}

// ---------------- kernel 3: fused scatter + pad-fill + y0 init --------------
__global__ void k_build_init(const int* __restrict__ row, const int* __restrict__ col,
                             const float* __restrict__ x, int n, int E) {
    int tidg = blockIdx.x * blockDim.x + threadIdx.x;

    if (tidg < E) {
        int r = row[tidg];
        g_csr[g_span[r].x + g_rank[tidg]] = col[tidg] * STRH;
    }

    if (tidg < n) {
        int2 sp = g_span[tidg];
        int dummy = n * STRH;
        for (int j = sp.x + g_deg[tidg]; j < sp.y; ++j) g_csr[j] = dummy;
    }

    int gw   = tidg >> 5;
    int lane = threadIdx.x & 31;
    __shared__ float cs[64];
    int needc = g_need_colmean;
    if (needc) { if (threadIdx.x < 64) cs[threadIdx.x] = 0.f; __syncthreads(); }
    float2 v = make_float2(0.f, 0.f);
    if (gw < n) {
        if (lane < 25 && g_isknown[gw])
            v = *(const float2*)(x + (size_t)gw * D + 2 * lane);
        float2 m = ((const float2*)g_mean)[lane];
        v.x -= m.x; v.y -= m.y;
        float di = g_dinv[gw];
        if (lane < 25)
            *(__half2*)(g_bufA + (size_t)gw * STRH + 2 * lane) =
                __floats2half2_rn(di * v.x, di * v.y);
    }
    if (needc) {
        if (gw < n && lane < 25) {
            atomicAdd(&cs[2 * lane],     v.x);
            atomicAdd(&cs[2 * lane + 1], v.y);
        }
        __syncthreads();
        if (threadIdx.x < D) atomicAdd(&g_colsum[threadIdx.x], cs[threadIdx.x]);
    }
}

// ---------------- the hot loop: one propagation step ------------------------
// ONE-WAVE grid (888 blocks); each warp strides over ~14 nodes. Normal cached
// loads (launch boundary flushes L1, so cross-iteration coherence is free).
__global__ __launch_bounds__(256) void k_iter(const float* __restrict__ x,
                                              float* __restrict__ fout,
                                              int n, float invn, int t, int last) {
    const int tid   = threadIdx.x;
    const int lane  = tid & 31;
    const int tidg0 = blockIdx.x * blockDim.x + tid;
    const int nthr  = gridDim.x * blockDim.x;
    const int wid0  = tidg0 >> 5;
    const int W     = nthr >> 5;
    __shared__ float cs[64];
    const int needc = g_need_colmean;
    const int needb = g_need_beta;
    if (needc) { if (tid < 64) cs[tid] = 0.f; __syncthreads(); }

    // epilogue/prologue zeroing for the NEXT call (readers all in the past)
    if (t == 0) for (int i = tidg0; i < n; i += nthr) g_deg[i] = 0;
    if (last) {
        if (tidg0 < 64) g_meansum[tidg0] = 0.f;
        if (tidg0 == 0) g_ctr = 0;
    }

    const __half* in  = (t & 1) ? g_bufB : g_bufA;
    __half*       out = (t & 1) ? g_bufA : g_bufB;
    const float* cs_in  = g_colsum + t * 64;
    float*       cs_out = g_colsum + (t + 1) * 64;

    #pragma unroll 1
    for (int gw = wid0; gw < n; gw += W) {
        int2 sp = g_span[gw];                     // one 8B uniform load
        int s = sp.x, e = sp.y;                   // 16B aligned, mult of 4
        const __half* inp = in + 2 * lane;
        float2 acc = make_float2(0.f, 0.f);
        int i = s;
        for (; i + 8 <= e; i += 8) {
            int4 c0 = *(const int4*)(g_csr + i);
            int4 c1 = *(const int4*)(g_csr + i + 4);
            float2 v0 = __half22float2(*(const __half2*)(inp + c0.x));
            float2 v1 = __half22float2(*(const __half2*)(inp + c0.y));
            float2 v2 = __half22float2(*(const __half2*)(inp + c0.z));
            float2 v3 = __half22float2(*(const __half2*)(inp + c0.w));
            float2 v4 = __half22float2(*(const __half2*)(inp + c1.x));
            float2 v5 = __half22float2(*(const __half2*)(inp + c1.y));
            float2 v6 = __half22float2(*(const __half2*)(inp + c1.z));
            float2 v7 = __half22float2(*(const __half2*)(inp + c1.w));
            acc.x += v0.x + v1.x + v2.x + v3.x + v4.x + v5.x + v6.x + v7.x;
            acc.y += v0.y + v1.y + v2.y + v3.y + v4.y + v5.y + v6.y + v7.y;
        }
        for (; i < e; i += 4) {
            int4 c0 = *(const int4*)(g_csr + i);
            float2 v0 = __half22float2(*(const __half2*)(inp + c0.x));
            float2 v1 = __half22float2(*(const __half2*)(inp + c0.y));
            float2 v2 = __half22float2(*(const __half2*)(inp + c0.z));
            float2 v3 = __half22float2(*(const __half2*)(inp + c0.w));
            acc.x += v0.x + v1.x + v2.x + v3.x;
            acc.y += v0.y + v1.y + v2.y + v3.y;
        }
        float di = g_dinv[gw];
        float2 v;
        if (needc) {
            float2 a  = ((const float2*)g_alpha)[lane];
            float2 om = ((const float2*)g_oma)[lane];
            v.x = fmaf(a.x, di * acc.x, om.x * (cs_in[2 * lane]     * invn));
            v.y = fmaf(a.y, di * acc.y, om.y * (cs_in[2 * lane + 1] * invn));
        } else {
            v.x = di * acc.x;                     // alpha == 1 exactly
            v.y = di * acc.y;
        }
        if (needb && g_isknown[gw]) {
            float2 b  = ((const float2*)g_beta)[lane];
            float2 ob = ((const float2*)g_omb)[lane];
            float2 m  = ((const float2*)g_mean)[lane];
            float2 xv = make_float2(0.f, 0.f);
            if (lane < 25) xv = *(const float2*)(x + (size_t)gw * D + 2 * lane);
            v.x = b.x * v.x + ob.x * (xv.x - m.x);
            v.y = b.y * v.y + ob.y * (xv.y - m.y);
        }
        if (last) {
            float2 m = ((const float2*)g_mean)[lane];
            if (lane < 25)
                *(float2*)(fout + (size_t)gw * D + 2 * lane) =
                    make_float2(v.x + m.x, v.y + m.y);
        } else {
            if (lane < 25)
                *(__half2*)(out + (size_t)gw * STRH + 2 * lane) =
                    __floats2half2_rn(di * v.x, di * v.y);
        }
        if (needc && lane < 25) {
            atomicAdd(&cs[2 * lane],     v.x);
            atomicAdd(&cs[2 * lane + 1], v.y);
        }
    }

    if (needc && !last) {
        __syncthreads();
        if (tid < D) atomicAdd(&cs_out[tid], cs[tid]);
    }
}

// ---------------- launcher ---------------------------------------------------
extern "C" void kernel_launch(void* const* d_in, const int* in_sizes, int n_in,
                              void* d_out, int out_size) {
    const float* x     = (const float*)d_in[0];
    const float* eta   = (const float*)d_in[1];
    const float* theta = (const float*)d_in[2];
    const int*   ei    = (const int*)d_in[3];
    const int*   km    = (const int*)d_in[4];

    int dd = in_sizes[1];              // 50
    int n  = in_sizes[0] / dd;         // 100000
    int E  = in_sizes[3] / 2;          // 1600000
    int K  = in_sizes[4];              // 50000
    const int* row = ei;
    const int* col = ei + E;

    const int TB = 256;
    int nbN = (n + TB - 1) / TB;       // 391 — one resident wave (safe to spin)
    int nbE = (E + TB - 1) / TB;
    int nbW = (n * 32 + TB - 1) / TB;  // warp-per-node grid for build_init

    k_deg_known_mean<<<nbE, TB>>>(row, km, x, E, K);
    k_scan_params   <<<nbN, TB>>>(n, eta, theta, K);
    k_build_init    <<<nbW, TB>>>(row, col, x, n, E);

    float invn = 1.f / (float)n;
    for (int t = 0; t < NITER; ++t) {
        k_iter<<<PBLK, TB>>>(x, (float*)d_out, n, invn, t, (t == NITER - 1) ? 1 : 0);
    }
}

// round 14
// speedup vs baseline: 1.5482x; 1.3853x over previous
#include <cuda_runtime.h>
#include <cuda_fp16.h>

// ---------------- problem-size constants (fixed by the dataset) -------------
#define N_MAX   100032      // >= 100000 nodes
#define E_MAX   1600000
#define E_PAD   2001600     // E + 4*N padding headroom
#define D       50          // attrs
#define STRH    64          // padded row stride of fp16 buffers (64 halves = 128B)
#define NITER   30
#define SCAN_B  256

// ---------------- static device scratch (no allocations allowed) ------------
// Invariants at call entry (static zero on load; restored by each call):
//   g_deg == 0 (zeroed in k_iter t==0), g_meansum == 0 and g_ctr == 0
//   (zeroed in k_iter t==NITER-1). g_colsum zeroed inside k_scan_params.
__device__ int    g_deg[N_MAX];
__device__ int2   g_span[N_MAX];         // {start, end} per node (one 8B load)
__device__ int    g_rank[E_MAX];         // per-edge rank within its row
__device__ int    g_partial[512];
__device__ int    g_ctr;                 // scan grid-barrier arrival counter
__device__ int    g_csr[E_PAD];          // col*STRH (half offset); dummies -> row n
__device__ float  g_dinv[N_MAX];
__device__ unsigned char g_isknown[N_MAX];   // idempotent sets; never cleared
__device__ float  g_meansum[64];
__device__ float  g_mean[64];            // pads [50,64) stay 0 forever
__device__ float  g_alpha[64];
__device__ float  g_oma[64];
__device__ float  g_beta[64];
__device__ float  g_omb[64];
__device__ float  g_colsum[(NITER + 1) * 64];
__device__ int    g_need_colmean;        // set iff any alpha != 1
__device__ int    g_need_beta;
// zero-initialized; rows >= n are NEVER written, so dummy gathers read 0.
__device__ __half g_bufA[(size_t)N_MAX * STRH];
__device__ __half g_bufB[(size_t)N_MAX * STRH];

// ---------------- kernel 1: degrees(+rank) + isknown + mean partials --------
__global__ void k_deg_known_mean(const int* __restrict__ row,
                                 const int* __restrict__ km,
                                 const float* __restrict__ x, int E, int K) {
    int i = blockIdx.x * blockDim.x + threadIdx.x;
    if (i < E) g_rank[i] = atomicAdd(&g_deg[row[i]], 1);
    if (i < K) g_isknown[km[i]] = 1;
    if (blockIdx.x < 100) {
        __shared__ float sm[64];
        if (threadIdx.x < 64) sm[threadIdx.x] = 0.f;
        __syncthreads();
        int lane = threadIdx.x & 31;
        int w  = (blockIdx.x * blockDim.x + threadIdx.x) >> 5;
        int nw = (100 * blockDim.x) >> 5;
        float2 acc = make_float2(0.f, 0.f);
        for (int k = w; k < K; k += nw) {
            int idx = km[k];
            if (lane < 25) {
                float2 vv = *(const float2*)(x + (size_t)idx * D + 2 * lane);
                acc.x += vv.x; acc.y += vv.y;
            }
        }
        if (lane < 25) {
            atomicAdd(&sm[2 * lane],     acc.x);
            atomicAdd(&sm[2 * lane + 1], acc.y);
        }
        __syncthreads();
        if (threadIdx.x < D) atomicAdd(&g_meansum[threadIdx.x], sm[threadIdx.x]);
    }
}

// ---------------- kernel 2: fused scan + spans + params (grid barrier) ------
// grid = ceil(n/256) = 391 blocks — fits in one resident wave; spin is safe.
__global__ void k_scan_params(int n, const float* __restrict__ eta,
                              const float* __restrict__ theta, int K) {
    __shared__ int s[SCAN_B];
    __shared__ int red[SCAN_B];
    __shared__ int fc, fb;
    int b = blockIdx.x, t = threadIdx.x;
    int i = b * SCAN_B + t;
    int nb = gridDim.x;

    if (i < (NITER + 1) * 64) g_colsum[i] = 0.f;

    int dg = (i < n) ? g_deg[i] : 0;
    if (i < n) g_dinv[i] = (dg > 0) ? rsqrtf((float)dg) : 0.f;
    int v = (dg + 3) & ~3;                      // padded length
    s[t] = v;
    __syncthreads();
    for (int d = 1; d < SCAN_B; d <<= 1) {
        int tmp = (t >= d) ? s[t - d] : 0;
        __syncthreads();
        s[t] += tmp;
        __syncthreads();
    }
    int excl = s[t] - v;
    if (t == SCAN_B - 1) {
        g_partial[b] = s[SCAN_B - 1];
        __threadfence();
    }
    __syncthreads();

    if (b == 0) {
        if (t == 0) { fc = 0; fb = 0; }
        __syncthreads();
        if (t < D) {
            g_mean[t] = g_meansum[t] / (float)K;
            float nf = (float)n;
            float a  = (nf - 1.f) / (theta[t] * nf + (nf - 1.f));
            float ia = 1.f / a;
            float bb = ia / (ia + eta[t]);
            g_alpha[t] = a;  g_oma[t] = 1.f - a;
            g_beta[t]  = bb; g_omb[t] = 1.f - bb;
            if (a  != 1.f) atomicExch(&fc, 1);
            if (bb != 1.f) atomicExch(&fb, 1);
        }
        __syncthreads();
        if (t == 0) { g_need_colmean = fc; g_need_beta = fb; }
    }

    if (t == 0) {
        atomicAdd(&g_ctr, 1);
        while (*(volatile int*)&g_ctr < nb) { }
    }
    __syncthreads();
    __threadfence();

    int local = 0;
    for (int j = t; j < b; j += SCAN_B) local += g_partial[j];
    red[t] = local;
    __syncthreads();
    for (int off = SCAN_B / 2; off > 0; off >>= 1) {
        if (t < off) red[t] += red[t + off];
        __syncthreads();
    }
    int base = red[0];

    if (i < n) {
        int s0 = base + excl;
        g_span[i] = make_int2(s0, s0 + v);
    }
}

// ---------------- kernel 3: fused scatter + pad-fill + y0 init --------------
__global__ void k_build_init(const int* __restrict__ row, const int* __restrict__ col,
                             const float* __restrict__ x, int n, int E) {
    int tidg = blockIdx.x * blockDim.x + threadIdx.x;

    if (tidg < E) {
        int r = row[tidg];
        g_csr[g_span[r].x + g_rank[tidg]] = col[tidg] * STRH;
    }

    if (tidg < n) {
        int2 sp = g_span[tidg];
        int dummy = n * STRH;
        for (int j = sp.x + g_deg[tidg]; j < sp.y; ++j) g_csr[j] = dummy;
    }

    int gw   = tidg >> 5;
    int lane = threadIdx.x & 31;
    __shared__ float cs[64];
    int needc = g_need_colmean;
    if (needc) { if (threadIdx.x < 64) cs[threadIdx.x] = 0.f; __syncthreads(); }
    float2 v = make_float2(0.f, 0.f);
    if (gw < n) {
        if (lane < 25 && g_isknown[gw])
            v = *(const float2*)(x + (size_t)gw * D + 2 * lane);
        float2 m = ((const float2*)g_mean)[lane];
        v.x -= m.x; v.y -= m.y;
        float di = g_dinv[gw];
        if (lane < 25)
            *(__half2*)(g_bufA + (size_t)gw * STRH + 2 * lane) =
                __floats2half2_rn(di * v.x, di * v.y);
    }
    if (needc) {
        if (gw < n && lane < 25) {
            atomicAdd(&cs[2 * lane],     v.x);
            atomicAdd(&cs[2 * lane + 1], v.y);
        }
        __syncthreads();
        if (threadIdx.x < D) atomicAdd(&g_colsum[threadIdx.x], cs[threadIdx.x]);
    }
}

// ---------------- the hot loop: one propagation step (proven R6/R9 shape) ---
// warp-per-node, 12500 blocks (32 regs, ~83% occ — the measured-best shape).
// fp16 gathers via the read-only path (__ldg: in-buffer is read-only within
// a launch), fp32 accumulation.
__global__ __launch_bounds__(256) void k_iter(const float* __restrict__ x,
                                              float* __restrict__ fout,
                                              int n, float invn, int t, int last) {
    int tidg = blockIdx.x * blockDim.x + threadIdx.x;
    int gw   = tidg >> 5;
    int lane = threadIdx.x & 31;
    __shared__ float cs[64];
    const int needc = g_need_colmean;
    if (needc) { if (threadIdx.x < 64) cs[threadIdx.x] = 0.f; __syncthreads(); }

    // epilogue/prologue zeroing for the NEXT call (readers all in the past)
    if (t == 0 && tidg < n) g_deg[tidg] = 0;
    if (last) {
        if (tidg < 64) g_meansum[tidg] = 0.f;
        if (tidg == 0) g_ctr = 0;
    }

    const __half* in  = (t & 1) ? g_bufB : g_bufA;
    __half*       out = (t & 1) ? g_bufA : g_bufB;
    const float* cs_in  = g_colsum + t * 64;
    float*       cs_out = g_colsum + (t + 1) * 64;

    float2 v = make_float2(0.f, 0.f);
    if (gw < n) {
        int2 sp = g_span[gw];                     // one 8B uniform load
        int s = sp.x, e = sp.y;                   // 16B aligned, mult of 4
        const __half2* inp = (const __half2*)(in + 2 * lane);
        float2 acc = make_float2(0.f, 0.f);
        int i = s;
        for (; i + 8 <= e; i += 8) {
            int4 c0 = *(const int4*)(g_csr + i);
            int4 c1 = *(const int4*)(g_csr + i + 4);
            float2 v0 = __half22float2(__ldg((const __half2*)((const __half*)inp + c0.x)));
            float2 v1 = __half22float2(__ldg((const __half2*)((const __half*)inp + c0.y)));
            float2 v2 = __half22float2(__ldg((const __half2*)((const __half*)inp + c0.z)));
            float2 v3 = __half22float2(__ldg((const __half2*)((const __half*)inp + c0.w)));
            float2 v4 = __half22float2(__ldg((const __half2*)((const __half*)inp + c1.x)));
            float2 v5 = __half22float2(__ldg((const __half2*)((const __half*)inp + c1.y)));
            float2 v6 = __half22float2(__ldg((const __half2*)((const __half*)inp + c1.z)));
            float2 v7 = __half22float2(__ldg((const __half2*)((const __half*)inp + c1.w)));
            acc.x += v0.x + v1.x + v2.x + v3.x + v4.x + v5.x + v6.x + v7.x;
            acc.y += v0.y + v1.y + v2.y + v3.y + v4.y + v5.y + v6.y + v7.y;
        }
        for (; i < e; i += 4) {
            int4 c0 = *(const int4*)(g_csr + i);
            float2 v0 = __half22float2(__ldg((const __half2*)((const __half*)inp + c0.x)));
            float2 v1 = __half22float2(__ldg((const __half2*)((const __half*)inp + c0.y)));
            float2 v2 = __half22float2(__ldg((const __half2*)((const __half*)inp + c0.z)));
            float2 v3 = __half22float2(__ldg((const __half2*)((const __half*)inp + c0.w)));
            acc.x += v0.x + v1.x + v2.x + v3.x;
            acc.y += v0.y + v1.y + v2.y + v3.y;
        }
        float di = g_dinv[gw];
        if (needc) {
            float2 a  = ((const float2*)g_alpha)[lane];
            float2 om = ((const float2*)g_oma)[lane];
            v.x = fmaf(a.x, di * acc.x, om.x * (cs_in[2 * lane]     * invn));
            v.y = fmaf(a.y, di * acc.y, om.y * (cs_in[2 * lane + 1] * invn));
        } else {
            v.x = di * acc.x;                     // alpha == 1 exactly
            v.y = di * acc.y;
        }
        if (g_need_beta && g_isknown[gw]) {
            float2 b  = ((const float2*)g_beta)[lane];
            float2 ob = ((const float2*)g_omb)[lane];
            float2 m  = ((const float2*)g_mean)[lane];
            float2 xv = make_float2(0.f, 0.f);
            if (lane < 25) xv = *(const float2*)(x + (size_t)gw * D + 2 * lane);
            v.x = b.x * v.x + ob.x * (xv.x - m.x);
            v.y = b.y * v.y + ob.y * (xv.y - m.y);
        }
        if (last) {
            float2 m = ((const float2*)g_mean)[lane];
            if (lane < 25)
                *(float2*)(fout + (size_t)gw * D + 2 * lane) =
                    make_float2(v.x + m.x, v.y + m.y);
        } else {
            if (lane < 25)
                *(__half2*)(out + (size_t)gw * STRH + 2 * lane) =
                    __floats2half2_rn(di * v.x, di * v.y);
        }
    }
    if (needc && !last) {
        if (gw < n && lane < 25) {
            atomicAdd(&cs[2 * lane],     v.x);
            atomicAdd(&cs[2 * lane + 1], v.y);
        }
        __syncthreads();
        if (threadIdx.x < D) atomicAdd(&cs_out[threadIdx.x], cs[threadIdx.x]);
    }
}

// ---------------- launcher ---------------------------------------------------
extern "C" void kernel_launch(void* const* d_in, const int* in_sizes, int n_in,
                              void* d_out, int out_size) {
    const float* x     = (const float*)d_in[0];
    const float* eta   = (const float*)d_in[1];
    const float* theta = (const float*)d_in[2];
    const int*   ei    = (const int*)d_in[3];
    const int*   km    = (const int*)d_in[4];

    int dd = in_sizes[1];              // 50
    int n  = in_sizes[0] / dd;         // 100000
    int E  = in_sizes[3] / 2;          // 1600000
    int K  = in_sizes[4];              // 50000
    const int* row = ei;
    const int* col = ei + E;

    const int TB = 256;
    int nbN = (n + TB - 1) / TB;       // 391 — one resident wave (safe to spin)
    int nbE = (E + TB - 1) / TB;
    int nbW = (n * 32 + TB - 1) / TB;  // warp-per-node grids (>= E threads)

    k_deg_known_mean<<<nbE, TB>>>(row, km, x, E, K);
    k_scan_params   <<<nbN, TB>>>(n, eta, theta, K);
    k_build_init    <<<nbW, TB>>>(row, col, x, n, E);

    float invn = 1.f / (float)n;
    for (int t = 0; t < NITER; ++t) {
        k_iter<<<nbW, TB>>>(x, (float*)d_out, n, invn, t, (t == NITER - 1) ? 1 : 0);
    }
}